// round 2
// baseline (speedup 1.0000x reference)
#include <cuda_runtime.h>
#include <stdint.h>
#include <stddef.h>

#define D 256
#define LMAX 100000
#define CMAX 50000

// ---- scratch (device globals: allocation-free per harness rules) ----
__device__ float g_hid  [(size_t)LMAX * D];  // hidden layer scratch (L rows covers C rows too)
__device__ float g_lfeat[(size_t)LMAX * D];  // l2c message features
__device__ float g_l2l  [(size_t)LMAX * D];  // l2l message
__device__ float g_laggr[(size_t)LMAX * D];  // c->l aggregation
__device__ float g_cfeat[(size_t)CMAX * D];  // c2l message features
__device__ float g_caggr[(size_t)CMAX * D];  // l->c aggregation

// ============================================================================
// Fused GEMM: Out[M,256] = act( sum_s A_s[M,256] @ W[s*256:(s+1)*256, :] + bias )
// Up to 3 A segments (for the concat-MLPs). swapA0: row r of A0 reads row r^1
// (the literal<->negated-literal pair swap).
// Tile: BM=128, BN=128, BK=8, 256 threads, 8x8 per-thread microtile.
// ============================================================================
#define BM 128
#define BN 128
#define BK 8

__global__ __launch_bounds__(256, 2) void gemm_fused(
    const float* __restrict__ A0, const float* __restrict__ A1,
    const float* __restrict__ A2,
    const float* __restrict__ W,      // [nseg*256, 256] row-major
    const float* __restrict__ bias,   // [256]
    float* __restrict__ Out,          // [M, 256]
    int M, int nseg, int swapA0, int relu)
{
    __shared__ float As[BK][BM];
    __shared__ float Bs[BK][BN];

    const int tid = threadIdx.x;
    const int block_row = blockIdx.y * BM;
    const int block_col = blockIdx.x * BN;

    float acc[8][8];
    #pragma unroll
    for (int i = 0; i < 8; i++)
        #pragma unroll
        for (int j = 0; j < 8; j++) acc[i][j] = 0.0f;

    const float* Aseg[3] = {A0, A1, A2};

    for (int s = 0; s < nseg; s++) {
        const float* A = Aseg[s];
        const float* Wseg = W + (size_t)s * D * D;
        const bool swap = (s == 0) && swapA0;

        for (int k0 = 0; k0 < D; k0 += BK) {
            // Load A tile: 128 rows x 8 k (one float4 per thread)
            {
                int r  = tid >> 1;            // 0..127
                int kq = (tid & 1) * 4;       // 0 or 4
                int row = block_row + r;
                float4 v = make_float4(0.f, 0.f, 0.f, 0.f);
                if (row < M) {
                    int arow = swap ? (row ^ 1) : row;
                    v = *reinterpret_cast<const float4*>(A + (size_t)arow * D + k0 + kq);
                }
                As[kq + 0][r] = v.x;
                As[kq + 1][r] = v.y;
                As[kq + 2][r] = v.z;
                As[kq + 3][r] = v.w;
            }
            // Load B tile: 8 k x 128 n (one float4 per thread)
            {
                int k  = tid >> 5;            // 0..7
                int nq = (tid & 31) * 4;      // 0..124
                float4 v = *reinterpret_cast<const float4*>(
                    Wseg + (size_t)(k0 + k) * D + block_col + nq);
                *reinterpret_cast<float4*>(&Bs[k][nq]) = v;
            }
            __syncthreads();

            const int ty = tid >> 4;   // 0..15
            const int tx = tid & 15;   // 0..15
            #pragma unroll
            for (int k = 0; k < BK; k++) {
                float a[8], b[8];
                *reinterpret_cast<float4*>(&a[0]) = *reinterpret_cast<const float4*>(&As[k][ty * 8]);
                *reinterpret_cast<float4*>(&a[4]) = *reinterpret_cast<const float4*>(&As[k][ty * 8 + 4]);
                *reinterpret_cast<float4*>(&b[0]) = *reinterpret_cast<const float4*>(&Bs[k][tx * 8]);
                *reinterpret_cast<float4*>(&b[4]) = *reinterpret_cast<const float4*>(&Bs[k][tx * 8 + 4]);
                #pragma unroll
                for (int i = 0; i < 8; i++)
                    #pragma unroll
                    for (int j = 0; j < 8; j++)
                        acc[i][j] += a[i] * b[j];
            }
            __syncthreads();
        }
    }

    // Epilogue: bias (+ relu), vectorized store
    const int ty = tid >> 4;
    const int tx = tid & 15;
    #pragma unroll
    for (int i = 0; i < 8; i++) {
        int row = block_row + ty * 8 + i;
        if (row >= M) continue;
        #pragma unroll
        for (int j = 0; j < 8; j += 4) {
            int col = block_col + tx * 8 + j;
            float4 v;
            v.x = acc[i][j + 0] + bias[col + 0];
            v.y = acc[i][j + 1] + bias[col + 1];
            v.z = acc[i][j + 2] + bias[col + 2];
            v.w = acc[i][j + 3] + bias[col + 3];
            if (relu) {
                v.x = fmaxf(v.x, 0.f); v.y = fmaxf(v.y, 0.f);
                v.z = fmaxf(v.z, 0.f); v.w = fmaxf(v.w, 0.f);
            }
            *reinterpret_cast<float4*>(Out + (size_t)row * D + col) = v;
        }
    }
}

// ============================================================================
// Edge scatter-add: dst[dstIdx[e]] += src[srcIdx[e]]   (rows of 256 floats)
// One thread per (edge, float4-chunk): 64 chunks per edge.
// ============================================================================
__global__ void scatter_add_kernel(
    const float4* __restrict__ src, const int* __restrict__ srcIdx,
    const int* __restrict__ dstIdx, float* __restrict__ dst, int E)
{
    long long idx = (long long)blockIdx.x * blockDim.x + threadIdx.x;
    if (idx >= (long long)E * 64) return;
    int e = (int)(idx >> 6);
    int c = (int)(idx & 63);
    float4 v = src[(size_t)srcIdx[e] * 64 + c];
    // dst is float*: row stride is 256 floats (D), chunk offset c*4 floats.
    float* d = dst + ((size_t)dstIdx[e] * (size_t)D + (size_t)c * 4);
    atomicAdd(d + 0, v.x);
    atomicAdd(d + 1, v.y);
    atomicAdd(d + 2, v.z);
    atomicAdd(d + 3, v.w);
}

// ============================================================================
// Launcher
// ============================================================================
extern "C" void kernel_launch(void* const* d_in, const int* in_sizes, int n_in,
                              void* d_out, int out_size)
{
    // Input layout: optional leading {l_size, c_size} scalars, then
    // ledge, cedge, l_emb, c_emb, then 5 MLPs x {W1,b1,W2,b2}.
    int base = n_in - 24;   // 26 inputs -> base 2 (scalars present), 24 -> base 0
    if (base < 0) base = 0;

    const int*   ledge  = (const int*)  d_in[base + 0];
    const int*   cedge  = (const int*)  d_in[base + 1];
    const float* l_emb0 = (const float*)d_in[base + 2];
    const float* c_emb0 = (const float*)d_in[base + 3];

    const int E = in_sizes[base + 0];
    const int L = in_sizes[base + 2] / D;
    const int C = in_sizes[base + 3] / D;

    const float* mlp[5][4]; // [l2c, c2l, l2l, cu, lu] x [W1,b1,W2,b2]
    for (int m = 0; m < 5; m++)
        for (int p = 0; p < 4; p++)
            mlp[m][p] = (const float*)d_in[base + 4 + m * 4 + p];

    const float *l2cW1 = mlp[0][0], *l2cb1 = mlp[0][1], *l2cW2 = mlp[0][2], *l2cb2 = mlp[0][3];
    const float *c2lW1 = mlp[1][0], *c2lb1 = mlp[1][1], *c2lW2 = mlp[1][2], *c2lb2 = mlp[1][3];
    const float *l2lW1 = mlp[2][0], *l2lb1 = mlp[2][1], *l2lW2 = mlp[2][2], *l2lb2 = mlp[2][3];
    const float *cuW1  = mlp[3][0], *cub1  = mlp[3][1], *cuW2  = mlp[3][2], *cub2  = mlp[3][3];
    const float *luW1  = mlp[4][0], *lub1  = mlp[4][1], *luW2  = mlp[4][2], *lub2  = mlp[4][3];

    // Scratch symbol addresses (query each call; cheap, capture-safe, no statics)
    float *hid, *lfeat, *l2lbuf, *laggr, *cfeat, *caggr;
    cudaGetSymbolAddress((void**)&hid,    g_hid);
    cudaGetSymbolAddress((void**)&lfeat,  g_lfeat);
    cudaGetSymbolAddress((void**)&l2lbuf, g_l2l);
    cudaGetSymbolAddress((void**)&laggr,  g_laggr);
    cudaGetSymbolAddress((void**)&cfeat,  g_cfeat);
    cudaGetSymbolAddress((void**)&caggr,  g_caggr);

    // Output: [5, L, D] l_embs followed by [5, C, D] c_embs
    float* l_hist = (float*)d_out;
    float* c_hist = l_hist + (size_t)5 * L * D;

    const size_t LD = (size_t)L * D;
    const size_t CD = (size_t)C * D;

    cudaMemcpyAsync(l_hist, l_emb0, LD * sizeof(float), cudaMemcpyDeviceToDevice);
    cudaMemcpyAsync(c_hist, c_emb0, CD * sizeof(float), cudaMemcpyDeviceToDevice);

    const dim3 blk(256);
    const dim3 gridL(2, (L + BM - 1) / BM);
    const dim3 gridC(2, (C + BM - 1) / BM);
    const int sc_threads = 256;
    const int sc_blocks = (int)(((long long)E * 64 + sc_threads - 1) / sc_threads);

    for (int t = 0; t < 4; t++) {
        const float* lpre = l_hist + (size_t)t * LD;
        const float* cpre = c_hist + (size_t)t * CD;
        float* lnew = l_hist + (size_t)(t + 1) * LD;
        float* cnew = c_hist + (size_t)(t + 1) * CD;

        // l2c message features: lfeat = MLP_l2c(lpre)
        gemm_fused<<<gridL, blk>>>(lpre, nullptr, nullptr, l2cW1, l2cb1, hid,   L, 1, 0, 1);
        gemm_fused<<<gridL, blk>>>(hid,  nullptr, nullptr, l2cW2, l2cb2, lfeat, L, 1, 0, 0);

        // c2l message features: cfeat = MLP_c2l(cpre)
        gemm_fused<<<gridC, blk>>>(cpre, nullptr, nullptr, c2lW1, c2lb1, hid,   C, 1, 0, 1);
        gemm_fused<<<gridC, blk>>>(hid,  nullptr, nullptr, c2lW2, c2lb2, cfeat, C, 1, 0, 0);

        // l2l message: l2lbuf = MLP_l2l(pair-swapped lpre)
        gemm_fused<<<gridL, blk>>>(lpre, nullptr, nullptr, l2lW1, l2lb1, hid,    L, 1, 1, 1);
        gemm_fused<<<gridL, blk>>>(hid,  nullptr, nullptr, l2lW2, l2lb2, l2lbuf, L, 1, 0, 0);

        // clause aggregation: caggr[c] = sum_{e: cedge[e]=c} lfeat[ledge[e]]
        cudaMemsetAsync(caggr, 0, CD * sizeof(float));
        scatter_add_kernel<<<sc_blocks, sc_threads>>>(
            (const float4*)lfeat, ledge, cedge, caggr, E);

        // clause update: cnew = MLP_cu([cpre, caggr])
        gemm_fused<<<gridC, blk>>>(cpre, caggr, nullptr, cuW1, cub1, hid, C, 2, 0, 1);
        gemm_fused<<<gridC, blk>>>(hid, nullptr, nullptr, cuW2, cub2, cnew, C, 1, 0, 0);

        // literal aggregation: laggr[l] = sum_{e: ledge[e]=l} cfeat[cedge[e]]
        cudaMemsetAsync(laggr, 0, LD * sizeof(float));
        scatter_add_kernel<<<sc_blocks, sc_threads>>>(
            (const float4*)cfeat, cedge, ledge, laggr, E);

        // literal update: lnew = MLP_lu([lpre, laggr, l2lbuf])
        gemm_fused<<<gridL, blk>>>(lpre, laggr, l2lbuf, luW1, lub1, hid, L, 3, 0, 1);
        gemm_fused<<<gridL, blk>>>(hid, nullptr, nullptr, luW2, lub2, lnew, L, 1, 0, 0);
    }
}